// round 16
// baseline (speedup 1.0000x reference)
#include <cuda_runtime.h>
#include <cuda_fp16.h>
#include <math.h>
#include <stdint.h>

#define T_SEQ 4096
#define HID   2048
#define NH    16
#define NKV   2
#define HD    128
#define QKV_N ((NH + 2*NKV)*HD)   // 2560
#define GQA   (NH/NKV)            // 8
#define VOFF  ((NH + NKV) * HD)   // 2304

// ---------------------------------------------------------------------------
// Device-global scratch
// ---------------------------------------------------------------------------
__device__ __half g_hid[4096 * 2048];
__device__ __half g_wq[2560 * 2048];
__device__ __half g_wo[2048 * 2048];
__device__ __half g_qkvh[4096 * 2560];
__device__ __half g_attn[4096 * 2048];
__device__ float g_cos[4096 * 64];
__device__ float g_sin[4096 * 64];

// ---------------------------------------------------------------------------
// Helpers
// ---------------------------------------------------------------------------
__device__ __forceinline__ uint32_t su32(const void* p) {
    uint32_t a;
    asm("{ .reg .u64 t; cvta.to.shared.u64 t, %1; cvt.u32.u64 %0, t; }"
        : "=r"(a) : "l"(p));
    return a;
}
__device__ __forceinline__ void ldsm4(uint32_t* r, uint32_t addr) {
    asm volatile("ldmatrix.sync.aligned.m8n8.x4.shared.b16 {%0,%1,%2,%3}, [%4];"
                 : "=r"(r[0]), "=r"(r[1]), "=r"(r[2]), "=r"(r[3]) : "r"(addr));
}
__device__ __forceinline__ void ldsm4t(uint32_t* r, uint32_t addr) {
    asm volatile("ldmatrix.sync.aligned.m8n8.x4.trans.shared.b16 {%0,%1,%2,%3}, [%4];"
                 : "=r"(r[0]), "=r"(r[1]), "=r"(r[2]), "=r"(r[3]) : "r"(addr));
}
__device__ __forceinline__ void mma16816h(float* c, const uint32_t* a,
                                          uint32_t b0, uint32_t b1) {
    asm volatile(
        "mma.sync.aligned.m16n8k16.row.col.f32.f16.f16.f32 "
        "{%0,%1,%2,%3}, {%4,%5,%6,%7}, {%8,%9}, {%0,%1,%2,%3};"
        : "+f"(c[0]), "+f"(c[1]), "+f"(c[2]), "+f"(c[3])
        : "r"(a[0]), "r"(a[1]), "r"(a[2]), "r"(a[3]), "r"(b0), "r"(b1));
}
__device__ __forceinline__ void cp_async16ca(uint32_t smem, const void* g) {
    asm volatile("cp.async.ca.shared.global [%0], [%1], 16;" :: "r"(smem), "l"(g));
}
#define CP_COMMIT() asm volatile("cp.async.commit_group;" ::: "memory")
#define CP_WAIT0()  asm volatile("cp.async.wait_group 0;" ::: "memory")
#define CP_WAIT1()  asm volatile("cp.async.wait_group 1;" ::: "memory")

__device__ __forceinline__ float ex2f(float x) {
    float y;
    asm("ex2.approx.ftz.f32 %0, %1;" : "=f"(y) : "f"(x));
    return y;
}
__device__ __forceinline__ uint32_t packh(float x, float y) {
    __half2 t = __floats2half2_rn(x, y);
    return *(uint32_t*)&t;
}

#define QSC (0.08838834764831845f * 1.4426950408889634f)  // 1/sqrt(HD) * log2(e)

// ---------------------------------------------------------------------------
// Fused prep kernel: fp32->fp16 conversions (hidden, w_qkv, w_o) + RoPE table.
// Conversion tasks first (vectorized float4), table tasks appended.
// ---------------------------------------------------------------------------
__global__ void prep_all(const float* __restrict__ a, __half* __restrict__ oa, int na,
                         const float* __restrict__ b, __half* __restrict__ ob, int nb,
                         const float* __restrict__ c, __half* __restrict__ oc, int nc,
                         const int* __restrict__ pos,
                         float* __restrict__ ct, float* __restrict__ st)
{
    int gid = blockIdx.x * blockDim.x + threadIdx.x;
    int nconv = (na + nb + nc) / 4;
    if (gid < nconv) {
        int i = gid * 4;
        const float* src;
        __half* dst;
        if (i < na)           { src = a + i;            dst = oa + i; }
        else if (i < na + nb) { src = b + (i - na);     dst = ob + (i - na); }
        else                  { src = c + (i - na - nb); dst = oc + (i - na - nb); }
        float4 v = *(const float4*)src;
        __half2 x = __floats2half2_rn(v.x, v.y);
        __half2 y = __floats2half2_rn(v.z, v.w);
        *(uint2*)dst = make_uint2(*(uint32_t*)&x, *(uint32_t*)&y);
        return;
    }
    int idx = gid - nconv;
    if (idx >= T_SEQ * (HD / 2)) return;
    int d = idx & 63;
    int t = idx >> 6;
    double inv = exp(-((double)(2 * d) / (double)HD) * 9.210340371976184);
    double ang = (double)pos[t] * inv;
    ct[idx] = (float)cos(ang);
    st[idx] = (float)sin(ang);
}

// ===========================================================================
// 1-term fp16 GEMM: C = A @ B^T (+bias). 128x128, BK=32, 8 warps,
// 2-stage cp.async (16B .ca), pointer-increment loader.
// Epilogue modes (vout != nullptr => QKV mode):
//   - QKV, bn >= VOFF: V tile -> fp16 direct to vout
//   - QKV, bn <  VOFF: q/k tile -> smem-staged RoPE (ct/st) -> fp16 to vout
//   - vout == nullptr: plain fp32 C write (o-proj)
// ===========================================================================
#define GS 40
#define MATB (128 * GS * 2)
#define G1_STAGE (2 * 128 * GS)
#define G1_SMEM  (2 * G1_STAGE * 2)         // 40960 bytes

__global__ void __launch_bounds__(256, 2)
gemm_1t(const __half* __restrict__ A_g, const __half* __restrict__ B_g,
        const float* __restrict__ bias, float* __restrict__ C,
        __half* __restrict__ vout,
        const float* __restrict__ ct, const float* __restrict__ st,
        int M, int N, int K)
{
    extern __shared__ __half smg[];
    const int tid = threadIdx.x, wid = tid >> 5, lane = tid & 31;
    const int bm = blockIdx.y * 128, bn = blockIdx.x * 128;
    const int wm = (wid & 3) * 32, wn = (wid >> 2) * 64;
    const uint32_t smb = su32(smg);

    float acc[2][8][4];
#pragma unroll
    for (int i = 0; i < 2; i++)
#pragma unroll
        for (int n = 0; n < 8; n++)
#pragma unroll
            for (int e = 0; e < 4; e++) acc[i][n][e] = 0.f;

    const int S = K / 32;

    const __half* gsrc[4];
    uint32_t gdstb[4];
#pragma unroll
    for (int i = 0; i < 4; i++) {
        int c = tid + i * 256;
        int mat = c >> 9;
        int w = c & 511;
        int row = w >> 2, cc = w & 3;
        const __half* s0 = (mat == 0)
            ? A_g + (size_t)(bm + row) * K
            : B_g + (size_t)(bn + row) * K;
        gsrc[i] = s0 + cc * 8;
        gdstb[i] = (uint32_t)((mat * (128 * GS) + row * GS + cc * 8) * 2);
    }
    auto issue = [&](int buf) {
        const uint32_t sb = smb + buf * (G1_STAGE * 2);
#pragma unroll
        for (int i = 0; i < 4; i++) {
            cp_async16ca(sb + gdstb[i], gsrc[i]);
            gsrc[i] += 32;
        }
    };

    issue(0); CP_COMMIT();

    const int a_r = lane & 15, a_k = (lane >> 4) * 8;
    const int b_n = ((lane >> 3) & 1) * 8 + (lane & 7), b_k = (lane >> 4) * 8;
    const uint32_t a_base = 2 * ((wm + a_r) * GS + a_k);
    const uint32_t b_base = 2 * ((wn + b_n) * GS + b_k);

    for (int s = 0; s < S; s++) {
        if (s + 1 < S) { issue((s + 1) & 1); CP_COMMIT(); CP_WAIT1(); }
        else CP_WAIT0();
        __syncthreads();

        const uint32_t stb = smb + (s & 1) * (G1_STAGE * 2);
        const uint32_t pA = stb + a_base;
        const uint32_t pB = stb + MATB + b_base;

#pragma unroll
        for (int kk = 0; kk < 2; kk++) {
            const uint32_t ko = kk * 32;
            uint32_t ah[2][4];
            ldsm4(ah[0], pA + ko);
            ldsm4(ah[1], pA + ko + 16 * GS * 2);
#pragma unroll
            for (int np = 0; np < 4; np++) {
                uint32_t bh[4];
                ldsm4(bh, pB + ko + np * (16 * GS * 2));
                mma16816h(acc[0][np * 2],     ah[0], bh[0], bh[2]);
                mma16816h(acc[0][np * 2 + 1], ah[0], bh[1], bh[3]);
                mma16816h(acc[1][np * 2],     ah[1], bh[0], bh[2]);
                mma16816h(acc[1][np * 2 + 1], ah[1], bh[1], bh[3]);
            }
        }
        __syncthreads();
    }

    const int tr = lane >> 2;
    const int tc = (lane & 3) * 2;

    if (vout == nullptr) {
        // ---- o-proj: fp32 C ----
#pragma unroll
        for (int i = 0; i < 2; i++) {
#pragma unroll
            for (int n = 0; n < 8; n++) {
                int col = bn + wn + n * 8 + tc;
                int row0 = bm + wm + i * 16 + tr;
                *(float2*)&C[(size_t)row0 * N + col] =
                    make_float2(acc[i][n][0], acc[i][n][1]);
                *(float2*)&C[(size_t)(row0 + 8) * N + col] =
                    make_float2(acc[i][n][2], acc[i][n][3]);
            }
        }
    } else if (bn >= VOFF) {
        // ---- V tile: +bias, fp16 direct ----
#pragma unroll
        for (int i = 0; i < 2; i++) {
#pragma unroll
            for (int n = 0; n < 8; n++) {
                int col = bn + wn + n * 8 + tc;
                float bb0 = bias[col], bb1 = bias[col + 1];
                int row0 = bm + wm + i * 16 + tr;
                __half2 hA = __floats2half2_rn(acc[i][n][0] + bb0,
                                               acc[i][n][1] + bb1);
                __half2 hB = __floats2half2_rn(acc[i][n][2] + bb0,
                                               acc[i][n][3] + bb1);
                *(__half2*)&vout[(size_t)row0 * N + col]       = hA;
                *(__half2*)&vout[(size_t)(row0 + 8) * N + col] = hB;
            }
        }
    } else {
        // ---- q/k tile: smem-staged RoPE, two 64-row halves ----
        float* Sf = (float*)smg;           // 64 x 128 fp32 = 32768 B
        const bool isq = (bn < NH * HD);
#pragma unroll
        for (int h2 = 0; h2 < 2; h2++) {
            __syncthreads();
            if (((wid & 3) >> 1) == h2) {
                int lr = wm - h2 * 64;     // 0 or 32
#pragma unroll
                for (int i = 0; i < 2; i++) {
#pragma unroll
                    for (int n = 0; n < 8; n++) {
                        int col = wn + n * 8 + tc;
                        float bb0 = bias[bn + col], bb1 = bias[bn + col + 1];
                        int r0l = lr + i * 16 + tr;
                        *(float2*)&Sf[r0l * 128 + col] =
                            make_float2(acc[i][n][0] + bb0, acc[i][n][1] + bb1);
                        *(float2*)&Sf[(r0l + 8) * 128 + col] =
                            make_float2(acc[i][n][2] + bb0, acc[i][n][3] + bb1);
                    }
                }
            }
            __syncthreads();
#pragma unroll
            for (int k = 0; k < 4; k++) {
                int task = tid + k * 256;
                int r = task >> 4;            // 0..63
                int d = (task & 15) * 4;      // 0..60
                int t = bm + h2 * 64 + r;
                float4 x1 = *(float4*)&Sf[r * 128 + d];
                float4 x2 = *(float4*)&Sf[r * 128 + d + 64];
                float4 c = *(const float4*)(ct + t * 64 + d);
                float4 s = *(const float4*)(st + t * 64 + d);
                float4 y1, y2;
                y1.x = x1.x * c.x - x2.x * s.x;  y2.x = x2.x * c.x + x1.x * s.x;
                y1.y = x1.y * c.y - x2.y * s.y;  y2.y = x2.y * c.y + x1.y * s.y;
                y1.z = x1.z * c.z - x2.z * s.z;  y2.z = x2.z * c.z + x1.z * s.z;
                y1.w = x1.w * c.w - x2.w * s.w;  y2.w = x2.w * c.w + x1.w * s.w;
                if (isq) {
                    y1.x *= QSC; y1.y *= QSC; y1.z *= QSC; y1.w *= QSC;
                    y2.x *= QSC; y2.y *= QSC; y2.z *= QSC; y2.w *= QSC;
                }
                size_t o = (size_t)t * QKV_N + bn + d;
                __half2 a1 = __floats2half2_rn(y1.x, y1.y);
                __half2 b1 = __floats2half2_rn(y1.z, y1.w);
                __half2 a2 = __floats2half2_rn(y2.x, y2.y);
                __half2 b2 = __floats2half2_rn(y2.z, y2.w);
                *(uint2*)(vout + o)      = make_uint2(*(uint32_t*)&a1, *(uint32_t*)&b1);
                *(uint2*)(vout + o + 64) = make_uint2(*(uint32_t*)&a2, *(uint32_t*)&b2);
            }
        }
    }
}

// ===========================================================================
// fp16 HMMA flash attention (best-measured config). 64-row q-tiles,
// 128 threads, 2 CTAs/SM. Q single fp16 in registers; K single; V single.
// ===========================================================================
#define SKS 136
#define AT_QSZ (64 * SKS)                   // halves
#define AT_KSZ (64 * SKS)                   // halves per matrix
#define AT_STAGE (2 * AT_KSZ)               // halves per stage (Kh, Vh)
#define AT_STAGEB (AT_STAGE * 2)            // 34816 bytes
#define AT_SMEM (AT_QSZ * 2 + 2 * AT_STAGEB)  // 87040 bytes

__global__ void __launch_bounds__(128, 2)
attn_mma(const __half* __restrict__ qkvh,
         __half* __restrict__ out)
{
    extern __shared__ __half sma[];
    __half* Qs = sma;

    const int tid = threadIdx.x, wid = tid >> 5, lane = tid & 31;
    const int h = blockIdx.y;
    const int qt = (int)gridDim.x - 1 - (int)blockIdx.x;   // heavy tiles first
    const int qbase = qt * 64;
    const int g = h >> 3;
    const int qoff = h * HD;
    const int koff = NH * HD + g * HD;
    const uint32_t smb = su32(sma);

    // ---- load Q tile (64 rows) to smem ----
#pragma unroll
    for (int i = 0; i < 8; i++) {
        int c = tid + i * 128;
        int row = c >> 4, cc = c & 15;
        const __half* src = qkvh + (size_t)(qbase + row) * QKV_N + qoff + cc * 8;
        *(uint4*)(Qs + row * SKS + cc * 8) = *(const uint4*)src;
    }

    // KV loader: thread covers rows r0+8j (j<8) for Kh and Vh.
    const int r0 = tid >> 4;               // 0..7
    const int lcc = tid & 15;
    const __half* kptr = qkvh + (size_t)r0 * QKV_N + koff + lcc * 8;
    const uint32_t kd0 = (uint32_t)((r0 * SKS + lcc * 8) * 2);

    auto load_kv = [&](int buf) {
        const uint32_t sb = smb + AT_QSZ * 2 + buf * AT_STAGEB + kd0;
#pragma unroll
        for (int j = 0; j < 8; j++) {
            cp_async16ca(sb + j * (8 * SKS * 2), kptr + (size_t)j * 8 * QKV_N);
            cp_async16ca(sb + AT_KSZ * 2 + j * (8 * SKS * 2),
                         kptr + (size_t)j * 8 * QKV_N + 2 * HD);  // voff-koff=256
        }
        kptr += (size_t)64 * QKV_N;
    };

    const int nkt = qt + 1;
    load_kv(0); CP_COMMIT();

    const int wq = wid * 16;
    const int a_r = lane & 15, a_k = (lane >> 4) * 8;
    const int b_n = ((lane >> 3) & 1) * 8 + (lane & 7), b_k = (lane >> 4) * 8;

    const uint32_t pQ = smb + 2 * ((wq + a_r) * SKS + a_k);
    const uint32_t bk_base = 2 * (b_n * SKS + b_k);

    __syncthreads();   // Q stores visible
    uint32_t qf[8][4];
#pragma unroll
    for (int kk = 0; kk < 8; kk++) ldsm4(qf[kk], pQ + kk * 32);

    float o[16][4];
#pragma unroll
    for (int d = 0; d < 16; d++)
#pragma unroll
        for (int e = 0; e < 4; e++) o[d][e] = 0.f;
    float m0 = -1e30f, m1 = -1e30f, l0 = 0.f, l1 = 0.f;

    for (int kt = 0; kt < nkt; kt++) {
        if (kt + 1 < nkt) { load_kv((kt + 1) & 1); CP_COMMIT(); CP_WAIT1(); }
        else CP_WAIT0();
        __syncthreads();

        const uint32_t kvb = smb + AT_QSZ * 2 + (kt & 1) * AT_STAGEB;
        const uint32_t pK = kvb + bk_base;
        const uint32_t pV = kvb + AT_KSZ * 2 + bk_base;

        // ---- S = Qh @ Kh^T ----
        float s[8][4];
#pragma unroll
        for (int n = 0; n < 8; n++)
#pragma unroll
            for (int e = 0; e < 4; e++) s[n][e] = 0.f;

#pragma unroll
        for (int kk = 0; kk < 8; kk++) {
            const uint32_t ko = kk * 32;
            uint32_t kh[4][4];
#pragma unroll
            for (int g4 = 0; g4 < 4; g4++)
                ldsm4(kh[g4], pK + ko + g4 * (16 * SKS * 2));
#pragma unroll
            for (int g4 = 0; g4 < 4; g4++) {
                mma16816h(s[g4 * 2],     qf[kk], kh[g4][0], kh[g4][2]);
                mma16816h(s[g4 * 2 + 1], qf[kk], kh[g4][1], kh[g4][3]);
            }
        }

        // ---- causal mask (only diagonal tile) ----
        if (kt == qt) {
            const int kbase = kt * 64;
            int rg0 = qbase + wq + (lane >> 2);
#pragma unroll
            for (int n = 0; n < 8; n++) {
                int cg = kbase + n * 8 + (lane & 3) * 2;
                if (cg > rg0)         s[n][0] = -1e30f;
                if (cg + 1 > rg0)     s[n][1] = -1e30f;
                if (cg > rg0 + 8)     s[n][2] = -1e30f;
                if (cg + 1 > rg0 + 8) s[n][3] = -1e30f;
            }
        }

        // ---- online softmax (exp2 domain) ----
        float mx0 = -1e30f, mx1 = -1e30f;
#pragma unroll
        for (int n = 0; n < 8; n++) {
            mx0 = fmaxf(mx0, fmaxf(s[n][0], s[n][1]));
            mx1 = fmaxf(mx1, fmaxf(s[n][2], s[n][3]));
        }
        mx0 = fmaxf(mx0, __shfl_xor_sync(0xffffffffu, mx0, 1));
        mx0 = fmaxf(mx0, __shfl_xor_sync(0xffffffffu, mx0, 2));
        mx1 = fmaxf(mx1, __shfl_xor_sync(0xffffffffu, mx1, 1));
        mx1 = fmaxf(mx1, __shfl_xor_sync(0xffffffffu, mx1, 2));
        float mn0 = fmaxf(m0, mx0), mn1 = fmaxf(m1, mx1);
        float c0 = ex2f(m0 - mn0), c1 = ex2f(m1 - mn1);
        float rs0 = 0.f, rs1 = 0.f;
#pragma unroll
        for (int n = 0; n < 8; n++) {
            s[n][0] = ex2f(s[n][0] - mn0); rs0 += s[n][0];
            s[n][1] = ex2f(s[n][1] - mn0); rs0 += s[n][1];
            s[n][2] = ex2f(s[n][2] - mn1); rs1 += s[n][2];
            s[n][3] = ex2f(s[n][3] - mn1); rs1 += s[n][3];
        }
        rs0 += __shfl_xor_sync(0xffffffffu, rs0, 1);
        rs0 += __shfl_xor_sync(0xffffffffu, rs0, 2);
        rs1 += __shfl_xor_sync(0xffffffffu, rs1, 1);
        rs1 += __shfl_xor_sync(0xffffffffu, rs1, 2);
        l0 = l0 * c0 + rs0; l1 = l1 * c1 + rs1;
        m0 = mn0; m1 = mn1;
#pragma unroll
        for (int d = 0; d < 16; d++) {
            o[d][0] *= c0; o[d][1] *= c0;
            o[d][2] *= c1; o[d][3] *= c1;
        }

        // ---- P (single fp16, A-layout) ----
        uint32_t aP[4][4];
#pragma unroll
        for (int kb = 0; kb < 4; kb++) {
            float* f0 = s[2 * kb];
            float* f1 = s[2 * kb + 1];
            aP[kb][0] = packh(f0[0], f0[1]);
            aP[kb][1] = packh(f0[2], f0[3]);
            aP[kb][2] = packh(f1[0], f1[1]);
            aP[kb][3] = packh(f1[2], f1[3]);
        }

        // ---- O += P @ Vh ----
#pragma unroll
        for (int kb = 0; kb < 4; kb++) {
            const uint32_t pvb = pV + kb * (16 * SKS * 2);
#pragma unroll
            for (int dp = 0; dp < 4; dp++) {
                uint32_t vh0[4], vh1[4];
                ldsm4t(vh0, pvb + (2 * dp) * 32);
                ldsm4t(vh1, pvb + (2 * dp + 1) * 32);
                mma16816h(o[4 * dp],     aP[kb], vh0[0], vh0[1]);
                mma16816h(o[4 * dp + 1], aP[kb], vh0[2], vh0[3]);
                mma16816h(o[4 * dp + 2], aP[kb], vh1[0], vh1[1]);
                mma16816h(o[4 * dp + 3], aP[kb], vh1[2], vh1[3]);
            }
        }
        __syncthreads();
    }

    // ---- epilogue: O/l -> single fp16 ----
    float inv0 = 1.f / l0, inv1 = 1.f / l1;
    int row0 = qbase + wq + (lane >> 2);
    int colb = h * HD + (lane & 3) * 2;
#pragma unroll
    for (int dg = 0; dg < 16; dg++) {
        int col = colb + dg * 8;
        __half2 hA = __floats2half2_rn(o[dg][0] * inv0, o[dg][1] * inv0);
        __half2 hB = __floats2half2_rn(o[dg][2] * inv1, o[dg][3] * inv1);
        *(__half2*)(out + (size_t)row0 * HID + col)       = hA;
        *(__half2*)(out + (size_t)(row0 + 8) * HID + col) = hB;
    }
}

// ---------------------------------------------------------------------------
extern "C" void kernel_launch(void* const* d_in, const int* in_sizes, int n_in,
                              void* d_out, int out_size)
{
    const int*   positions = (const int*)d_in[0];
    const float* hidden    = (const float*)d_in[1];
    const float* w_qkv     = (const float*)d_in[2];
    const float* b_qkv     = (const float*)d_in[3];
    const float* w_o       = (const float*)d_in[4];
    float* out = (float*)d_out;

    float *ct, *st;
    __half *hid, *wq, *wo, *qkvh, *attn;
    cudaGetSymbolAddress((void**)&ct,   g_cos);
    cudaGetSymbolAddress((void**)&st,   g_sin);
    cudaGetSymbolAddress((void**)&hid,  g_hid);
    cudaGetSymbolAddress((void**)&wq,   g_wq);
    cudaGetSymbolAddress((void**)&wo,   g_wo);
    cudaGetSymbolAddress((void**)&qkvh, g_qkvh);
    cudaGetSymbolAddress((void**)&attn, g_attn);

    cudaFuncSetAttribute(gemm_1t,
                         cudaFuncAttributeMaxDynamicSharedMemorySize, G1_SMEM);
    cudaFuncSetAttribute(attn_mma,
                         cudaFuncAttributeMaxDynamicSharedMemorySize, AT_SMEM);

    // 0) fused prep: fp16 conversions + rope table in ONE launch
    {
        int n1 = T_SEQ * HID;        // hidden
        int n2 = QKV_N * HID;        // w_qkv
        int n3 = HID * HID;          // w_o
        int total = (n1 + n2 + n3) / 4 + T_SEQ * (HD / 2);
        prep_all<<<(total + 255) / 256, 256>>>(hidden, hid, n1,
                                               w_qkv, wq, n2,
                                               w_o, wo, n3,
                                               positions, ct, st);
    }

    // 1) qkv GEMM with fused epilogues: q/k tiles -> RoPE -> fp16,
    //    V tiles -> fp16 direct. No fp32 qkv round-trip.
    dim3 g1(QKV_N / 128, T_SEQ / 128);
    gemm_1t<<<g1, 256, G1_SMEM>>>(hid, wq, b_qkv, nullptr, qkvh, ct, st,
                                  T_SEQ, QKV_N, HID);

    // 2) flash attention (fp16 HMMA), 64-row q-tiles, 2 CTAs/SM
    attn_mma<<<dim3(T_SEQ / 64, NH), 128, AT_SMEM>>>(qkvh, attn);

    // 3) out = attn @ w_o^T (fp32 out)
    dim3 g2(HID / 128, T_SEQ / 128);
    gemm_1t<<<g2, 256, G1_SMEM>>>(attn, wo, nullptr, out, nullptr,
                                  nullptr, nullptr, T_SEQ, HID, HID);
}

// round 17
// speedup vs baseline: 1.0029x; 1.0029x over previous
#include <cuda_runtime.h>
#include <cuda_fp16.h>
#include <math.h>
#include <stdint.h>

#define T_SEQ 4096
#define HID   2048
#define NH    16
#define NKV   2
#define HD    128
#define QKV_N ((NH + 2*NKV)*HD)   // 2560
#define GQA   (NH/NKV)            // 8
#define VOFF  ((NH + NKV) * HD)   // 2304

// ---------------------------------------------------------------------------
// Device-global scratch
// ---------------------------------------------------------------------------
__device__ __half g_hid[4096 * 2048];
__device__ __half g_wq[2560 * 2048];
__device__ __half g_wo[2048 * 2048];
__device__ __half g_qkvh[4096 * 2560];
__device__ __half g_attn[4096 * 2048];
__device__ float g_cos[4096 * 64];
__device__ float g_sin[4096 * 64];

// ---------------------------------------------------------------------------
// Helpers
// ---------------------------------------------------------------------------
__device__ __forceinline__ uint32_t su32(const void* p) {
    uint32_t a;
    asm("{ .reg .u64 t; cvta.to.shared.u64 t, %1; cvt.u32.u64 %0, t; }"
        : "=r"(a) : "l"(p));
    return a;
}
__device__ __forceinline__ void ldsm4(uint32_t* r, uint32_t addr) {
    asm volatile("ldmatrix.sync.aligned.m8n8.x4.shared.b16 {%0,%1,%2,%3}, [%4];"
                 : "=r"(r[0]), "=r"(r[1]), "=r"(r[2]), "=r"(r[3]) : "r"(addr));
}
__device__ __forceinline__ void ldsm4t(uint32_t* r, uint32_t addr) {
    asm volatile("ldmatrix.sync.aligned.m8n8.x4.trans.shared.b16 {%0,%1,%2,%3}, [%4];"
                 : "=r"(r[0]), "=r"(r[1]), "=r"(r[2]), "=r"(r[3]) : "r"(addr));
}
__device__ __forceinline__ void mma16816h(float* c, const uint32_t* a,
                                          uint32_t b0, uint32_t b1) {
    asm volatile(
        "mma.sync.aligned.m16n8k16.row.col.f32.f16.f16.f32 "
        "{%0,%1,%2,%3}, {%4,%5,%6,%7}, {%8,%9}, {%0,%1,%2,%3};"
        : "+f"(c[0]), "+f"(c[1]), "+f"(c[2]), "+f"(c[3])
        : "r"(a[0]), "r"(a[1]), "r"(a[2]), "r"(a[3]), "r"(b0), "r"(b1));
}
__device__ __forceinline__ void cp_async16ca(uint32_t smem, const void* g) {
    asm volatile("cp.async.ca.shared.global [%0], [%1], 16;" :: "r"(smem), "l"(g));
}
#define CP_COMMIT() asm volatile("cp.async.commit_group;" ::: "memory")
#define CP_WAIT0()  asm volatile("cp.async.wait_group 0;" ::: "memory")
#define CP_WAIT1()  asm volatile("cp.async.wait_group 1;" ::: "memory")

__device__ __forceinline__ float ex2f(float x) {
    float y;
    asm("ex2.approx.ftz.f32 %0, %1;" : "=f"(y) : "f"(x));
    return y;
}
__device__ __forceinline__ uint32_t packh(float x, float y) {
    __half2 t = __floats2half2_rn(x, y);
    return *(uint32_t*)&t;
}

#define QSC (0.08838834764831845f * 1.4426950408889634f)  // 1/sqrt(HD) * log2(e)

// ---------------------------------------------------------------------------
// One fused conversion kernel: hidden, w_qkv, w_o -> fp16
// ---------------------------------------------------------------------------
__global__ void conv_all(const float* __restrict__ a, __half* __restrict__ oa, int na,
                         const float* __restrict__ b, __half* __restrict__ ob, int nb,
                         const float* __restrict__ c, __half* __restrict__ oc, int nc)
{
    int i = (blockIdx.x * blockDim.x + threadIdx.x) * 4;
    const float* src;
    __half* dst;
    if (i < na)            { src = a + i;            dst = oa + i; }
    else if (i < na + nb)  { src = b + (i - na);     dst = ob + (i - na); }
    else if (i < na + nb + nc) { src = c + (i - na - nb); dst = oc + (i - na - nb); }
    else return;
    float4 v = *(const float4*)src;
    __half2 x = __floats2half2_rn(v.x, v.y);
    __half2 y = __floats2half2_rn(v.z, v.w);
    *(uint2*)dst = make_uint2(*(uint32_t*)&x, *(uint32_t*)&y);
}

// ---------------------------------------------------------------------------
// RoPE cos/sin table
// ---------------------------------------------------------------------------
__global__ void rope_table_kernel(const int* __restrict__ pos,
                                  float* __restrict__ ct, float* __restrict__ st)
{
    int idx = blockIdx.x * blockDim.x + threadIdx.x;
    if (idx >= T_SEQ * (HD / 2)) return;
    int d = idx & 63;
    int t = idx >> 6;
    double inv = exp(-((double)(2 * d) / (double)HD) * 9.210340371976184);
    double ang = (double)pos[t] * inv;
    ct[idx] = (float)cos(ang);
    st[idx] = (float)sin(ang);
}

// ===========================================================================
// 1-term fp16 GEMM: C = A @ B^T (+bias). 128x128, BK=32, 8 warps,
// 2-stage cp.async (16B .ca), pointer-increment loader.
// Epilogue modes (vout != nullptr => QKV mode):
//   - QKV, bn >= VOFF: V tile -> fp16 direct to vout
//   - QKV, bn <  VOFF: q/k tile -> smem-staged RoPE (ct/st) -> fp16 to vout
//   - vout == nullptr: plain fp32 C write (o-proj)
// ===========================================================================
#define GS 40
#define MATB (128 * GS * 2)
#define G1_STAGE (2 * 128 * GS)
#define G1_SMEM  (2 * G1_STAGE * 2)         // 40960 bytes

__global__ void __launch_bounds__(256, 2)
gemm_1t(const __half* __restrict__ A_g, const __half* __restrict__ B_g,
        const float* __restrict__ bias, float* __restrict__ C,
        __half* __restrict__ vout,
        const float* __restrict__ ct, const float* __restrict__ st,
        int M, int N, int K)
{
    extern __shared__ __half smg[];
    const int tid = threadIdx.x, wid = tid >> 5, lane = tid & 31;
    const int bm = blockIdx.y * 128, bn = blockIdx.x * 128;
    const int wm = (wid & 3) * 32, wn = (wid >> 2) * 64;
    const uint32_t smb = su32(smg);

    float acc[2][8][4];
#pragma unroll
    for (int i = 0; i < 2; i++)
#pragma unroll
        for (int n = 0; n < 8; n++)
#pragma unroll
            for (int e = 0; e < 4; e++) acc[i][n][e] = 0.f;

    const int S = K / 32;

    const __half* gsrc[4];
    uint32_t gdstb[4];
#pragma unroll
    for (int i = 0; i < 4; i++) {
        int c = tid + i * 256;
        int mat = c >> 9;
        int w = c & 511;
        int row = w >> 2, cc = w & 3;
        const __half* s0 = (mat == 0)
            ? A_g + (size_t)(bm + row) * K
            : B_g + (size_t)(bn + row) * K;
        gsrc[i] = s0 + cc * 8;
        gdstb[i] = (uint32_t)((mat * (128 * GS) + row * GS + cc * 8) * 2);
    }
    auto issue = [&](int buf) {
        const uint32_t sb = smb + buf * (G1_STAGE * 2);
#pragma unroll
        for (int i = 0; i < 4; i++) {
            cp_async16ca(sb + gdstb[i], gsrc[i]);
            gsrc[i] += 32;
        }
    };

    issue(0); CP_COMMIT();

    const int a_r = lane & 15, a_k = (lane >> 4) * 8;
    const int b_n = ((lane >> 3) & 1) * 8 + (lane & 7), b_k = (lane >> 4) * 8;
    const uint32_t a_base = 2 * ((wm + a_r) * GS + a_k);
    const uint32_t b_base = 2 * ((wn + b_n) * GS + b_k);

    for (int s = 0; s < S; s++) {
        if (s + 1 < S) { issue((s + 1) & 1); CP_COMMIT(); CP_WAIT1(); }
        else CP_WAIT0();
        __syncthreads();

        const uint32_t stb = smb + (s & 1) * (G1_STAGE * 2);
        const uint32_t pA = stb + a_base;
        const uint32_t pB = stb + MATB + b_base;

#pragma unroll
        for (int kk = 0; kk < 2; kk++) {
            const uint32_t ko = kk * 32;
            uint32_t ah[2][4];
            ldsm4(ah[0], pA + ko);
            ldsm4(ah[1], pA + ko + 16 * GS * 2);
#pragma unroll
            for (int np = 0; np < 4; np++) {
                uint32_t bh[4];
                ldsm4(bh, pB + ko + np * (16 * GS * 2));
                mma16816h(acc[0][np * 2],     ah[0], bh[0], bh[2]);
                mma16816h(acc[0][np * 2 + 1], ah[0], bh[1], bh[3]);
                mma16816h(acc[1][np * 2],     ah[1], bh[0], bh[2]);
                mma16816h(acc[1][np * 2 + 1], ah[1], bh[1], bh[3]);
            }
        }
        __syncthreads();
    }

    const int tr = lane >> 2;
    const int tc = (lane & 3) * 2;

    if (vout == nullptr) {
        // ---- o-proj: fp32 C ----
#pragma unroll
        for (int i = 0; i < 2; i++) {
#pragma unroll
            for (int n = 0; n < 8; n++) {
                int col = bn + wn + n * 8 + tc;
                int row0 = bm + wm + i * 16 + tr;
                *(float2*)&C[(size_t)row0 * N + col] =
                    make_float2(acc[i][n][0], acc[i][n][1]);
                *(float2*)&C[(size_t)(row0 + 8) * N + col] =
                    make_float2(acc[i][n][2], acc[i][n][3]);
            }
        }
    } else if (bn >= VOFF) {
        // ---- V tile: +bias, fp16 direct ----
#pragma unroll
        for (int i = 0; i < 2; i++) {
#pragma unroll
            for (int n = 0; n < 8; n++) {
                int col = bn + wn + n * 8 + tc;
                float bb0 = bias[col], bb1 = bias[col + 1];
                int row0 = bm + wm + i * 16 + tr;
                __half2 hA = __floats2half2_rn(acc[i][n][0] + bb0,
                                               acc[i][n][1] + bb1);
                __half2 hB = __floats2half2_rn(acc[i][n][2] + bb0,
                                               acc[i][n][3] + bb1);
                *(__half2*)&vout[(size_t)row0 * N + col]       = hA;
                *(__half2*)&vout[(size_t)(row0 + 8) * N + col] = hB;
            }
        }
    } else {
        // ---- q/k tile: smem-staged RoPE, two 64-row halves ----
        float* Sf = (float*)smg;           // 64 x 128 fp32 = 32768 B
        const bool isq = (bn < NH * HD);
#pragma unroll
        for (int h2 = 0; h2 < 2; h2++) {
            __syncthreads();
            if (((wid & 3) >> 1) == h2) {
                int lr = wm - h2 * 64;     // 0 or 32
#pragma unroll
                for (int i = 0; i < 2; i++) {
#pragma unroll
                    for (int n = 0; n < 8; n++) {
                        int col = wn + n * 8 + tc;
                        float bb0 = bias[bn + col], bb1 = bias[bn + col + 1];
                        int r0l = lr + i * 16 + tr;
                        *(float2*)&Sf[r0l * 128 + col] =
                            make_float2(acc[i][n][0] + bb0, acc[i][n][1] + bb1);
                        *(float2*)&Sf[(r0l + 8) * 128 + col] =
                            make_float2(acc[i][n][2] + bb0, acc[i][n][3] + bb1);
                    }
                }
            }
            __syncthreads();
#pragma unroll
            for (int k = 0; k < 4; k++) {
                int task = tid + k * 256;
                int r = task >> 4;            // 0..63
                int d = (task & 15) * 4;      // 0..60
                int t = bm + h2 * 64 + r;
                float4 x1 = *(float4*)&Sf[r * 128 + d];
                float4 x2 = *(float4*)&Sf[r * 128 + d + 64];
                float4 c = *(const float4*)(ct + t * 64 + d);
                float4 s = *(const float4*)(st + t * 64 + d);
                float4 y1, y2;
                y1.x = x1.x * c.x - x2.x * s.x;  y2.x = x2.x * c.x + x1.x * s.x;
                y1.y = x1.y * c.y - x2.y * s.y;  y2.y = x2.y * c.y + x1.y * s.y;
                y1.z = x1.z * c.z - x2.z * s.z;  y2.z = x2.z * c.z + x1.z * s.z;
                y1.w = x1.w * c.w - x2.w * s.w;  y2.w = x2.w * c.w + x1.w * s.w;
                if (isq) {
                    y1.x *= QSC; y1.y *= QSC; y1.z *= QSC; y1.w *= QSC;
                    y2.x *= QSC; y2.y *= QSC; y2.z *= QSC; y2.w *= QSC;
                }
                size_t o = (size_t)t * QKV_N + bn + d;
                __half2 a1 = __floats2half2_rn(y1.x, y1.y);
                __half2 b1 = __floats2half2_rn(y1.z, y1.w);
                __half2 a2 = __floats2half2_rn(y2.x, y2.y);
                __half2 b2 = __floats2half2_rn(y2.z, y2.w);
                *(uint2*)(vout + o)      = make_uint2(*(uint32_t*)&a1, *(uint32_t*)&b1);
                *(uint2*)(vout + o + 64) = make_uint2(*(uint32_t*)&a2, *(uint32_t*)&b2);
            }
        }
    }
}

// ===========================================================================
// fp16 HMMA flash attention (best-measured config). 64-row q-tiles,
// 128 threads, 2 CTAs/SM. Q single fp16 in registers; K single; V single.
// ===========================================================================
#define SKS 136
#define AT_QSZ (64 * SKS)                   // halves
#define AT_KSZ (64 * SKS)                   // halves per matrix
#define AT_STAGE (2 * AT_KSZ)               // halves per stage (Kh, Vh)
#define AT_STAGEB (AT_STAGE * 2)            // 34816 bytes
#define AT_SMEM (AT_QSZ * 2 + 2 * AT_STAGEB)  // 87040 bytes

__global__ void __launch_bounds__(128, 2)
attn_mma(const __half* __restrict__ qkvh,
         __half* __restrict__ out)
{
    extern __shared__ __half sma[];
    __half* Qs = sma;

    const int tid = threadIdx.x, wid = tid >> 5, lane = tid & 31;
    const int h = blockIdx.y;
    const int qt = (int)gridDim.x - 1 - (int)blockIdx.x;   // heavy tiles first
    const int qbase = qt * 64;
    const int g = h >> 3;
    const int qoff = h * HD;
    const int koff = NH * HD + g * HD;
    const uint32_t smb = su32(sma);

    // ---- load Q tile (64 rows) to smem ----
#pragma unroll
    for (int i = 0; i < 8; i++) {
        int c = tid + i * 128;
        int row = c >> 4, cc = c & 15;
        const __half* src = qkvh + (size_t)(qbase + row) * QKV_N + qoff + cc * 8;
        *(uint4*)(Qs + row * SKS + cc * 8) = *(const uint4*)src;
    }

    // KV loader: thread covers rows r0+8j (j<8) for Kh and Vh.
    const int r0 = tid >> 4;               // 0..7
    const int lcc = tid & 15;
    const __half* kptr = qkvh + (size_t)r0 * QKV_N + koff + lcc * 8;
    const uint32_t kd0 = (uint32_t)((r0 * SKS + lcc * 8) * 2);

    auto load_kv = [&](int buf) {
        const uint32_t sb = smb + AT_QSZ * 2 + buf * AT_STAGEB + kd0;
#pragma unroll
        for (int j = 0; j < 8; j++) {
            cp_async16ca(sb + j * (8 * SKS * 2), kptr + (size_t)j * 8 * QKV_N);
            cp_async16ca(sb + AT_KSZ * 2 + j * (8 * SKS * 2),
                         kptr + (size_t)j * 8 * QKV_N + 2 * HD);  // voff-koff=256
        }
        kptr += (size_t)64 * QKV_N;
    };

    const int nkt = qt + 1;
    load_kv(0); CP_COMMIT();

    const int wq = wid * 16;
    const int a_r = lane & 15, a_k = (lane >> 4) * 8;
    const int b_n = ((lane >> 3) & 1) * 8 + (lane & 7), b_k = (lane >> 4) * 8;

    const uint32_t pQ = smb + 2 * ((wq + a_r) * SKS + a_k);
    const uint32_t bk_base = 2 * (b_n * SKS + b_k);

    __syncthreads();   // Q stores visible
    uint32_t qf[8][4];
#pragma unroll
    for (int kk = 0; kk < 8; kk++) ldsm4(qf[kk], pQ + kk * 32);

    float o[16][4];
#pragma unroll
    for (int d = 0; d < 16; d++)
#pragma unroll
        for (int e = 0; e < 4; e++) o[d][e] = 0.f;
    float m0 = -1e30f, m1 = -1e30f, l0 = 0.f, l1 = 0.f;

    for (int kt = 0; kt < nkt; kt++) {
        if (kt + 1 < nkt) { load_kv((kt + 1) & 1); CP_COMMIT(); CP_WAIT1(); }
        else CP_WAIT0();
        __syncthreads();

        const uint32_t kvb = smb + AT_QSZ * 2 + (kt & 1) * AT_STAGEB;
        const uint32_t pK = kvb + bk_base;
        const uint32_t pV = kvb + AT_KSZ * 2 + bk_base;

        // ---- S = Qh @ Kh^T ----
        float s[8][4];
#pragma unroll
        for (int n = 0; n < 8; n++)
#pragma unroll
            for (int e = 0; e < 4; e++) s[n][e] = 0.f;

#pragma unroll
        for (int kk = 0; kk < 8; kk++) {
            const uint32_t ko = kk * 32;
            uint32_t kh[4][4];
#pragma unroll
            for (int g4 = 0; g4 < 4; g4++)
                ldsm4(kh[g4], pK + ko + g4 * (16 * SKS * 2));
#pragma unroll
            for (int g4 = 0; g4 < 4; g4++) {
                mma16816h(s[g4 * 2],     qf[kk], kh[g4][0], kh[g4][2]);
                mma16816h(s[g4 * 2 + 1], qf[kk], kh[g4][1], kh[g4][3]);
            }
        }

        // ---- causal mask (only diagonal tile) ----
        if (kt == qt) {
            const int kbase = kt * 64;
            int rg0 = qbase + wq + (lane >> 2);
#pragma unroll
            for (int n = 0; n < 8; n++) {
                int cg = kbase + n * 8 + (lane & 3) * 2;
                if (cg > rg0)         s[n][0] = -1e30f;
                if (cg + 1 > rg0)     s[n][1] = -1e30f;
                if (cg > rg0 + 8)     s[n][2] = -1e30f;
                if (cg + 1 > rg0 + 8) s[n][3] = -1e30f;
            }
        }

        // ---- online softmax (exp2 domain) ----
        float mx0 = -1e30f, mx1 = -1e30f;
#pragma unroll
        for (int n = 0; n < 8; n++) {
            mx0 = fmaxf(mx0, fmaxf(s[n][0], s[n][1]));
            mx1 = fmaxf(mx1, fmaxf(s[n][2], s[n][3]));
        }
        mx0 = fmaxf(mx0, __shfl_xor_sync(0xffffffffu, mx0, 1));
        mx0 = fmaxf(mx0, __shfl_xor_sync(0xffffffffu, mx0, 2));
        mx1 = fmaxf(mx1, __shfl_xor_sync(0xffffffffu, mx1, 1));
        mx1 = fmaxf(mx1, __shfl_xor_sync(0xffffffffu, mx1, 2));
        float mn0 = fmaxf(m0, mx0), mn1 = fmaxf(m1, mx1);
        float c0 = ex2f(m0 - mn0), c1 = ex2f(m1 - mn1);
        float rs0 = 0.f, rs1 = 0.f;
#pragma unroll
        for (int n = 0; n < 8; n++) {
            s[n][0] = ex2f(s[n][0] - mn0); rs0 += s[n][0];
            s[n][1] = ex2f(s[n][1] - mn0); rs0 += s[n][1];
            s[n][2] = ex2f(s[n][2] - mn1); rs1 += s[n][2];
            s[n][3] = ex2f(s[n][3] - mn1); rs1 += s[n][3];
        }
        rs0 += __shfl_xor_sync(0xffffffffu, rs0, 1);
        rs0 += __shfl_xor_sync(0xffffffffu, rs0, 2);
        rs1 += __shfl_xor_sync(0xffffffffu, rs1, 1);
        rs1 += __shfl_xor_sync(0xffffffffu, rs1, 2);
        l0 = l0 * c0 + rs0; l1 = l1 * c1 + rs1;
        m0 = mn0; m1 = mn1;
#pragma unroll
        for (int d = 0; d < 16; d++) {
            o[d][0] *= c0; o[d][1] *= c0;
            o[d][2] *= c1; o[d][3] *= c1;
        }

        // ---- P (single fp16, A-layout) ----
        uint32_t aP[4][4];
#pragma unroll
        for (int kb = 0; kb < 4; kb++) {
            float* f0 = s[2 * kb];
            float* f1 = s[2 * kb + 1];
            aP[kb][0] = packh(f0[0], f0[1]);
            aP[kb][1] = packh(f0[2], f0[3]);
            aP[kb][2] = packh(f1[0], f1[1]);
            aP[kb][3] = packh(f1[2], f1[3]);
        }

        // ---- O += P @ Vh ----
#pragma unroll
        for (int kb = 0; kb < 4; kb++) {
            const uint32_t pvb = pV + kb * (16 * SKS * 2);
#pragma unroll
            for (int dp = 0; dp < 4; dp++) {
                uint32_t vh0[4], vh1[4];
                ldsm4t(vh0, pvb + (2 * dp) * 32);
                ldsm4t(vh1, pvb + (2 * dp + 1) * 32);
                mma16816h(o[4 * dp],     aP[kb], vh0[0], vh0[1]);
                mma16816h(o[4 * dp + 1], aP[kb], vh0[2], vh0[3]);
                mma16816h(o[4 * dp + 2], aP[kb], vh1[0], vh1[1]);
                mma16816h(o[4 * dp + 3], aP[kb], vh1[2], vh1[3]);
            }
        }
        __syncthreads();
    }

    // ---- epilogue: O/l -> single fp16 ----
    float inv0 = 1.f / l0, inv1 = 1.f / l1;
    int row0 = qbase + wq + (lane >> 2);
    int colb = h * HD + (lane & 3) * 2;
#pragma unroll
    for (int dg = 0; dg < 16; dg++) {
        int col = colb + dg * 8;
        __half2 hA = __floats2half2_rn(o[dg][0] * inv0, o[dg][1] * inv0);
        __half2 hB = __floats2half2_rn(o[dg][2] * inv1, o[dg][3] * inv1);
        *(__half2*)(out + (size_t)row0 * HID + col)       = hA;
        *(__half2*)(out + (size_t)(row0 + 8) * HID + col) = hB;
    }
}

// ---------------------------------------------------------------------------
extern "C" void kernel_launch(void* const* d_in, const int* in_sizes, int n_in,
                              void* d_out, int out_size)
{
    const int*   positions = (const int*)d_in[0];
    const float* hidden    = (const float*)d_in[1];
    const float* w_qkv     = (const float*)d_in[2];
    const float* b_qkv     = (const float*)d_in[3];
    const float* w_o       = (const float*)d_in[4];
    float* out = (float*)d_out;

    float *ct, *st;
    __half *hid, *wq, *wo, *qkvh, *attn;
    cudaGetSymbolAddress((void**)&ct,   g_cos);
    cudaGetSymbolAddress((void**)&st,   g_sin);
    cudaGetSymbolAddress((void**)&hid,  g_hid);
    cudaGetSymbolAddress((void**)&wq,   g_wq);
    cudaGetSymbolAddress((void**)&wo,   g_wo);
    cudaGetSymbolAddress((void**)&qkvh, g_qkvh);
    cudaGetSymbolAddress((void**)&attn, g_attn);

    cudaFuncSetAttribute(gemm_1t,
                         cudaFuncAttributeMaxDynamicSharedMemorySize, G1_SMEM);
    cudaFuncSetAttribute(attn_mma,
                         cudaFuncAttributeMaxDynamicSharedMemorySize, AT_SMEM);

    // 0) prep inputs (single fused conversion kernel) + rope table
    {
        int n1 = T_SEQ * HID;        // hidden
        int n2 = QKV_N * HID;        // w_qkv
        int n3 = HID * HID;          // w_o
        int total = (n1 + n2 + n3) / 4;
        conv_all<<<(total + 255) / 256, 256>>>(hidden, hid, n1,
                                               w_qkv, wq, n2,
                                               w_o, wo, n3);
        int nt = T_SEQ * (HD / 2);
        rope_table_kernel<<<(nt + 255) / 256, 256>>>(positions, ct, st);
    }

    // 1) qkv GEMM with fused epilogues: q/k tiles -> RoPE -> fp16,
    //    V tiles -> fp16 direct. No fp32 qkv round-trip.
    dim3 g1(QKV_N / 128, T_SEQ / 128);
    gemm_1t<<<g1, 256, G1_SMEM>>>(hid, wq, b_qkv, nullptr, qkvh, ct, st,
                                  T_SEQ, QKV_N, HID);

    // 2) flash attention (fp16 HMMA), 64-row q-tiles, 2 CTAs/SM
    attn_mma<<<dim3(T_SEQ / 64, NH), 128, AT_SMEM>>>(qkvh, attn);

    // 3) out = attn @ w_o^T (fp32 out)
    dim3 g2(HID / 128, T_SEQ / 128);
    gemm_1t<<<g2, 256, G1_SMEM>>>(attn, wo, nullptr, out, nullptr,
                                  nullptr, nullptr, T_SEQ, HID, HID);
}